// round 13
// baseline (speedup 1.0000x reference)
#include <cuda_runtime.h>
#include <cuda_bf16.h>
#include <cstdint>

// ============================================================================
// Problem constants
// ============================================================================
static constexpr int BB = 4;
static constexpr int SS_ = 4096;
static constexpr int DD = 1024;
static constexpr int MTOT = BB * SS_;            // 16384
static constexpr int NCHUNK_S = 32;
static constexpr int LCHUNK_S = SS_ / NCHUNK_S;  // 128
static constexpr size_t PLANE = (size_t)MTOT * DD;   // elements per bf16 plane

// GEMM tiling: CTA 128x256, K-chunk 64, 512 threads, 2-stage pipeline
static constexpr int BM = 128, BN = 256, BK = 64;
static constexpr int THREADS = 512;
static constexpr int A_TILE = BM * BK * 2;       // 16 KB per plane
static constexpr int B_TILE = BN * BK * 2;       // 32 KB per plane
static constexpr int STAGE_BYTES = 2 * A_TILE + 2 * B_TILE;   // 96 KB
static constexpr int STAGES = 2;
static constexpr int SMEM_GEMM_TOTAL = STAGES * STAGE_BYTES;  // 192 KB

// ============================================================================
// Device scratch — 88.5 MiB total (same single 128 MiB granule as R10/R12).
//   g_act: activation planes (hi, lo): avg -> h
//   dedicated transposed/split weight buffers (filled once, up front)
// ============================================================================
__device__ __nv_bfloat16 g_act[2 * PLANE];                      // 64 MiB
__device__ __nv_bfloat16 g_w1t_hi[(size_t)DD * DD];             // 2 MiB
__device__ __nv_bfloat16 g_w1t_lo[(size_t)DD * DD];
__device__ __nv_bfloat16 g_w2t_hi[(size_t)DD * DD];
__device__ __nv_bfloat16 g_w2t_lo[(size_t)DD * DD];
__device__ __nv_bfloat16 g_wgt_hi[(size_t)2 * DD * 2 * DD];     // 8 MiB
__device__ __nv_bfloat16 g_wgt_lo[(size_t)2 * DD * 2 * DD];     // 8 MiB
__device__ float         g_part[BB * NCHUNK_S * DD];            // 0.5 MiB

// ============================================================================
// PTX helpers (sm_80-era: valid on plain sm_100 target)
// ============================================================================
__device__ __forceinline__ uint32_t smem_to_u32(const void* smem_ptr) {
    uint32_t addr;
    asm("{ .reg .u64 tmp; cvta.to.shared.u64 tmp, %1; cvt.u32.u64 %0, tmp; }"
        : "=r"(addr) : "l"(smem_ptr));
    return addr;
}

__device__ __forceinline__ void cp_async16(uint32_t dst, const void* src) {
    asm volatile("cp.async.cg.shared.global [%0], [%1], 16;" :: "r"(dst), "l"(src));
}
#define CP_COMMIT() asm volatile("cp.async.commit_group;" ::: "memory")
#define CP_WAIT(n)  asm volatile("cp.async.wait_group %0;" :: "n"(n) : "memory")

__device__ __forceinline__ void ldsm_x4(uint32_t* r, uint32_t addr) {
    asm volatile("ldmatrix.sync.aligned.m8n8.x4.shared.b16 {%0,%1,%2,%3}, [%4];"
                 : "=r"(r[0]), "=r"(r[1]), "=r"(r[2]), "=r"(r[3]) : "r"(addr));
}

__device__ __forceinline__ void mma_16816(float* d, const uint32_t* a,
                                          uint32_t b0, uint32_t b1) {
    asm volatile(
        "mma.sync.aligned.m16n8k16.row.col.f32.bf16.bf16.f32 "
        "{%0,%1,%2,%3}, {%4,%5,%6,%7}, {%8,%9}, {%0,%1,%2,%3};"
        : "+f"(d[0]), "+f"(d[1]), "+f"(d[2]), "+f"(d[3])
        : "r"(a[0]), "r"(a[1]), "r"(a[2]), "r"(a[3]), "r"(b0), "r"(b1));
}

__device__ __forceinline__ uint32_t pack_hi2(float x, float y) {
    __nv_bfloat16 hx = __float2bfloat16(x), hy = __float2bfloat16(y);
    return (uint32_t)__bfloat16_as_ushort(hx) |
           ((uint32_t)__bfloat16_as_ushort(hy) << 16);
}
__device__ __forceinline__ uint32_t pack_lo2(float x, float y) {
    __nv_bfloat16 hx = __float2bfloat16(x), hy = __float2bfloat16(y);
    __nv_bfloat16 lx = __float2bfloat16(x - __bfloat162float(hx));
    __nv_bfloat16 ly = __float2bfloat16(y - __bfloat162float(hy));
    return (uint32_t)__bfloat16_as_ushort(lx) |
           ((uint32_t)__bfloat16_as_ushort(ly) << 16);
}
__device__ __forceinline__ float2 unpack_bf16x2(uint32_t u) {
    float2 r;
    r.x = __bfloat162float(__ushort_as_bfloat16((unsigned short)(u & 0xFFFF)));
    r.y = __bfloat162float(__ushort_as_bfloat16((unsigned short)(u >> 16)));
    return r;
}

// ============================================================================
// Fused weight transpose + hi/lo split for ALL weights (one launch).
//   z=0: W1 1024x1024 -> g_w1t ; z=1: W2 -> g_w2t ; z=2: Wg 2048x2048 -> g_wgt
// ============================================================================
__global__ void transpose_all_kernel(const float* __restrict__ W1,
                                     const float* __restrict__ W2,
                                     const float* __restrict__ Wg) {
    const int z = blockIdx.z;
    const float* W; __nv_bfloat16 *Th, *Tl; int Kdim, N;
    if (z == 0)      { W = W1; Th = g_w1t_hi; Tl = g_w1t_lo; Kdim = 1024; N = 1024; }
    else if (z == 1) { W = W2; Th = g_w2t_hi; Tl = g_w2t_lo; Kdim = 1024; N = 1024; }
    else             { W = Wg; Th = g_wgt_hi; Tl = g_wgt_lo; Kdim = 2048; N = 2048; }
    const int n0 = blockIdx.x * 32, k0 = blockIdx.y * 32;
    if (n0 >= N || k0 >= Kdim) return;
    __shared__ float t[32][33];
    const int tx = threadIdx.x, ty = threadIdx.y;
#pragma unroll
    for (int i = 0; i < 32; i += 8)
        t[ty + i][tx] = W[(size_t)(k0 + ty + i) * N + (n0 + tx)];
    __syncthreads();
#pragma unroll
    for (int i = 0; i < 32; i += 8) {
        float f = t[tx][ty + i];
        __nv_bfloat16 h = __float2bfloat16(f);
        __nv_bfloat16 q = __float2bfloat16(f - __bfloat162float(h));
        size_t o = (size_t)(n0 + ty + i) * Kdim + (k0 + tx);
        Th[o] = h; Tl[o] = q;
    }
}

// ============================================================================
// Prefix-mean (3-pass chunked scan over S) -> avg bf16 hi/lo planes in g_act
// ============================================================================
__global__ void cumsum_part_kernel(const float* __restrict__ iV) {
    const int b = blockIdx.z, dg = blockIdx.y, c = blockIdx.x;
    const int d = dg * 256 + threadIdx.x;
    const float* p = iV + ((size_t)b * SS_ + (size_t)c * LCHUNK_S) * DD + d;
    float acc = 0.f;
#pragma unroll 4
    for (int s = 0; s < LCHUNK_S; s++) acc += p[(size_t)s * DD];
    g_part[(b * NCHUNK_S + c) * DD + d] = acc;
}

__global__ void cumsum_scan_kernel() {
    const int b = blockIdx.y;
    const int d = blockIdx.x * 256 + threadIdx.x;
    float run = 0.f;
    for (int c = 0; c < NCHUNK_S; c++) {
        float v = g_part[(b * NCHUNK_S + c) * DD + d];
        g_part[(b * NCHUNK_S + c) * DD + d] = run;
        run += v;
    }
}

__global__ void cumsum_avg_kernel(const float* __restrict__ iV) {
    const int b = blockIdx.z, dg = blockIdx.y, c = blockIdx.x;
    const int d = dg * 256 + threadIdx.x;
    const size_t base = ((size_t)b * SS_ + (size_t)c * LCHUNK_S) * DD + d;
    const float* p = iV + base;
    float run = g_part[(b * NCHUNK_S + c) * DD + d];
#pragma unroll 4
    for (int s = 0; s < LCHUNK_S; s++) {
        run += p[(size_t)s * DD];
        float a = run / (float)(c * LCHUNK_S + s + 1);
        __nv_bfloat16 h = __float2bfloat16(a);
        __nv_bfloat16 l = __float2bfloat16(a - __bfloat162float(h));
        g_act[base + (size_t)s * DD] = h;
        g_act[PLANE + base + (size_t)s * DD] = l;
    }
}

// ============================================================================
// Split-bf16 GEMM, CTA 128x256, 512 threads, 2-stage pipeline.
//   C[M, *] = epi(A @ Bt^T + bias)
//   Chunks < nf32: A from Af32 (fp32, converted). Chunks >= nf32: A planes.
//   Per chunk: AhiBhi + AhiBlo + AloBhi into fp32 accs.
//   modes: 0 relu->planes; 1 plain->planes; 2 outf = sig(x)*epi_f32;
//          3 outf += sig(x)*(epi_hi+epi_lo)
// ============================================================================
__global__ void __launch_bounds__(THREADS, 1) gemm_split_kernel(
    const float* __restrict__ Af32,
    const __nv_bfloat16* __restrict__ Ahi, const __nv_bfloat16* __restrict__ Alo,
    const __nv_bfloat16* __restrict__ Bh,  const __nv_bfloat16* __restrict__ Bl,
    const float* __restrict__ bias,
    const float* __restrict__ epi_f32,
    const __nv_bfloat16* __restrict__ epi_hi, const __nv_bfloat16* __restrict__ epi_lo,
    float* __restrict__ out_f32,
    __nv_bfloat16* __restrict__ out_hi, __nv_bfloat16* __restrict__ out_lo,
    int K, int nf32, int mode)
{
    extern __shared__ __align__(16) char smem[];
    const uint32_t sbase = smem_to_u32(smem);
    const int tid = threadIdx.x;
    const int w = tid >> 5, l = tid & 31;
    const int wm = w & 3, wn = w >> 2;           // 4x4 warp grid; tile 32x64
    const int mbase = blockIdx.x * BM, nbase = blockIdx.y * BN;
    const int NC = K >> 6;

    float acc[2][8][4];
#pragma unroll
    for (int a = 0; a < 2; a++)
#pragma unroll
        for (int b = 0; b < 8; b++)
#pragma unroll
            for (int c = 0; c < 4; c++) acc[a][b][c] = 0.f;

    float4 areg[4];

    auto lda_f32 = [&](int ch) {
        const float* s = Af32 + (size_t)mbase * 1024 + (ch << 6);
#pragma unroll
        for (int i = 0; i < 4; i++) {
            const int cid = tid + i * THREADS;       // 2048 float4 cells
            const int r = cid >> 4, c = cid & 15;
            areg[i] = *(const float4*)(s + (size_t)r * 1024 + c * 4);
        }
    };
    auto sts_a = [&](int ch) {
        const uint32_t abuf = (uint32_t)((ch & 1) * STAGE_BYTES);
#pragma unroll
        for (int i = 0; i < 4; i++) {
            const int cid = tid + i * THREADS;
            const int r = cid >> 4, c = cid & 15;
            const uint32_t off = (uint32_t)(r * 128 + (((c >> 1) ^ (r & 7)) << 4)
                                            + (c & 1) * 8);
            float4 v = areg[i];
            uint2 hv, lv;
            hv.x = pack_hi2(v.x, v.y); hv.y = pack_hi2(v.z, v.w);
            lv.x = pack_lo2(v.x, v.y); lv.y = pack_lo2(v.z, v.w);
            *(uint2*)(smem + abuf + off) = hv;
            *(uint2*)(smem + abuf + A_TILE + off) = lv;
        }
    };
    auto lda_planes = [&](int ch) {
        const uint32_t abuf = sbase + (uint32_t)((ch & 1) * STAGE_BYTES);
        const int kk = (ch - nf32) << 6;
#pragma unroll
        for (int i = 0; i < 2; i++) {
            const int cid = tid + i * THREADS;       // 1024 16B cells
            const int r = cid >> 3, c = cid & 7;
            const uint32_t off = (uint32_t)(r * 128 + ((c ^ (r & 7)) << 4));
            const size_t gsrc = (size_t)(mbase + r) * 1024 + kk + c * 8;
            cp_async16(abuf + off, Ahi + gsrc);
            cp_async16(abuf + A_TILE + off, Alo + gsrc);
        }
    };
    auto ldb = [&](int ch) {
        const uint32_t bbuf = sbase + (uint32_t)((ch & 1) * STAGE_BYTES)
                              + 2 * A_TILE;
        const int kk = ch << 6;
#pragma unroll
        for (int i = 0; i < 4; i++) {
            const int cid = tid + i * THREADS;       // 2048 16B cells
            const int r = cid >> 3, c = cid & 7;
            const uint32_t off = (uint32_t)(r * 128 + ((c ^ (r & 7)) << 4));
            const size_t gsrc = (size_t)(nbase + r) * K + kk + c * 8;
            cp_async16(bbuf + off, Bh + gsrc);
            cp_async16(bbuf + B_TILE + off, Bl + gsrc);
        }
    };
    auto mma_chunk = [&](int ch) {
        const uint32_t sb = sbase + (uint32_t)((ch & 1) * STAGE_BYTES);
        const uint32_t ahiB = sb, aloB = sb + A_TILE;
        const uint32_t bhiB = sb + 2 * A_TILE, bloB = bhiB + B_TILE;
#pragma unroll
        for (int ks = 0; ks < 4; ks++) {
            const int cc = ks * 2 + (l >> 4);
            uint32_t ah[2][4], al[2][4];
#pragma unroll
            for (int mt = 0; mt < 2; mt++) {
                const int row = wm * 32 + mt * 16 + (l & 15);
                const uint32_t off = (uint32_t)(row * 128 + ((cc ^ (row & 7)) << 4));
                ldsm_x4(ah[mt], ahiB + off);
                ldsm_x4(al[mt], aloB + off);
            }
#pragma unroll
            for (int bt = 0; bt < 4; bt++) {
                const int row = wn * 64 + bt * 16 + (l & 15);
                const uint32_t off = (uint32_t)(row * 128 + ((cc ^ (row & 7)) << 4));
                uint32_t bh[4], bl[4];
                ldsm_x4(bh, bhiB + off);
                ldsm_x4(bl, bloB + off);
#pragma unroll
                for (int mt = 0; mt < 2; mt++) {
                    mma_16816(acc[mt][bt * 2],     ah[mt], bh[0], bh[2]);
                    mma_16816(acc[mt][bt * 2 + 1], ah[mt], bh[1], bh[3]);
                    mma_16816(acc[mt][bt * 2],     ah[mt], bl[0], bl[2]);
                    mma_16816(acc[mt][bt * 2 + 1], ah[mt], bl[1], bl[3]);
                    mma_16816(acc[mt][bt * 2],     al[mt], bh[0], bh[2]);
                    mma_16816(acc[mt][bt * 2 + 1], al[mt], bh[1], bh[3]);
                }
            }
        }
    };

    // ---- prologue: stage 0 ----
    {
        const bool f32c = (0 < nf32);
        if (f32c) lda_f32(0); else lda_planes(0);
        ldb(0);
        CP_COMMIT();
        if (f32c) sts_a(0);
    }

    // ---- main loop ----
    for (int ch = 0; ch < NC; ch++) {
        const int pf = ch + 1;
        const bool pf_valid = (pf < NC);
        const bool pf_f32 = pf_valid && (pf < nf32);
        if (pf_valid) {
            if (pf_f32) lda_f32(pf); else lda_planes(pf);
            ldb(pf);
        }
        CP_COMMIT();
        CP_WAIT(1);
        __syncthreads();
        if (pf_f32) sts_a(pf);      // writes stage (ch+1)&1; mma reads ch&1
        mma_chunk(ch);
        __syncthreads();
    }

    // ---- epilogue ----
    const int quad = l >> 2, qid = l & 3;
#pragma unroll
    for (int mt = 0; mt < 2; mt++) {
#pragma unroll
        for (int nt = 0; nt < 8; nt++) {
            const int col = nbase + wn * 64 + nt * 8 + qid * 2;
            const float2 bb = *(const float2*)(bias + col);
#pragma unroll
            for (int h2 = 0; h2 < 2; h2++) {
                const int r = mbase + wm * 32 + mt * 16 + quad + h2 * 8;
                float x = acc[mt][nt][h2 * 2 + 0] + bb.x;
                float y = acc[mt][nt][h2 * 2 + 1] + bb.y;
                const size_t idx = (size_t)r * 1024 + col;
                if (mode == 0 || mode == 1) {
                    if (mode == 0) { x = x > 0.f ? x : 0.f; y = y > 0.f ? y : 0.f; }
                    *(uint32_t*)(out_hi + idx) = pack_hi2(x, y);
                    *(uint32_t*)(out_lo + idx) = pack_lo2(x, y);
                } else {
                    float sx = 1.f / (1.f + __expf(-x));
                    float sy = 1.f / (1.f + __expf(-y));
                    if (mode == 2) {
                        const float2 e = *(const float2*)(epi_f32 + idx);
                        float2 v; v.x = sx * e.x; v.y = sy * e.y;
                        *(float2*)(out_f32 + idx) = v;
                    } else {
                        float2 eh = unpack_bf16x2(*(const uint32_t*)(epi_hi + idx));
                        float2 el = unpack_bf16x2(*(const uint32_t*)(epi_lo + idx));
                        float2 o = *(const float2*)(out_f32 + idx);
                        o.x += sx * (eh.x + el.x);
                        o.y += sy * (eh.y + el.y);
                        *(float2*)(out_f32 + idx) = o;
                    }
                }
            }
        }
    }
}

// ============================================================================
// Launch
//   Order chosen so ncu (-s 5 -c 1) profiles GEMM2 (launch #6):
//     1 transpose_all, 2 part, 3 scan, 4 avg, 5 g1, 6 g2, 7 g3a, 8 g3b
//   Plane plan: avg planes->g_act ; g1: g_act->d_out planes (u)
//     g2: d_out planes -> g_act planes (h)
//     g3a: A=[iQ f32, h planes]; out = sig(.)*iQ -> d_out fp32
//     g3b: same A; out += sig(.)*h
// ============================================================================
extern "C" void kernel_launch(void* const* d_in, const int* in_sizes, int n_in,
                              void* d_out, int out_size) {
    const float* iQ = (const float*)d_in[0];
    const float* iV = (const float*)d_in[1];
    const float* W1 = (const float*)d_in[2];
    const float* b1 = (const float*)d_in[3];
    const float* W2 = (const float*)d_in[4];
    const float* b2 = (const float*)d_in[5];
    const float* Wg = (const float*)d_in[6];
    const float* bg = (const float*)d_in[7];
    float* out = (float*)d_out;

    cudaFuncSetAttribute(gemm_split_kernel,
                         cudaFuncAttributeMaxDynamicSharedMemorySize,
                         SMEM_GEMM_TOTAL);

    __nv_bfloat16 *p_act = nullptr;
    __nv_bfloat16 *p_w1h = nullptr, *p_w1l = nullptr;
    __nv_bfloat16 *p_w2h = nullptr, *p_w2l = nullptr;
    __nv_bfloat16 *p_wgh = nullptr, *p_wgl = nullptr;
    cudaGetSymbolAddress((void**)&p_act, g_act);
    cudaGetSymbolAddress((void**)&p_w1h, g_w1t_hi);
    cudaGetSymbolAddress((void**)&p_w1l, g_w1t_lo);
    cudaGetSymbolAddress((void**)&p_w2h, g_w2t_hi);
    cudaGetSymbolAddress((void**)&p_w2l, g_w2t_lo);
    cudaGetSymbolAddress((void**)&p_wgh, g_wgt_hi);
    cudaGetSymbolAddress((void**)&p_wgl, g_wgt_lo);
    __nv_bfloat16* act_hi = p_act;
    __nv_bfloat16* act_lo = p_act + PLANE;
    __nv_bfloat16* dout_hi = (__nv_bfloat16*)out;
    __nv_bfloat16* dout_lo = (__nv_bfloat16*)out + PLANE;

    // 1: all weight transposes (one launch)
    transpose_all_kernel<<<dim3(64, 64, 3), dim3(32, 8)>>>(W1, W2, Wg);

    // 2-4: prefix-mean over S -> avg planes in g_act
    cumsum_part_kernel<<<dim3(NCHUNK_S, DD / 256, BB), 256>>>(iV);
    cumsum_scan_kernel<<<dim3(DD / 256, BB), 256>>>();
    cumsum_avg_kernel<<<dim3(NCHUNK_S, DD / 256, BB), 256>>>(iV);

    const dim3 ggrid(MTOT / BM, 1024 / BN);   // (128, 4)

    // 5: GEMM1  u = relu(avg @ W1 + b1)    g_act planes -> d_out planes
    gemm_split_kernel<<<ggrid, THREADS, SMEM_GEMM_TOTAL>>>(
        nullptr, act_hi, act_lo, p_w1h, p_w1l, b1,
        nullptr, nullptr, nullptr, nullptr, dout_hi, dout_lo, 1024, 0, 0);

    // 6: GEMM2  h = u @ W2 + b2            d_out planes -> g_act planes
    gemm_split_kernel<<<ggrid, THREADS, SMEM_GEMM_TOTAL>>>(
        nullptr, dout_hi, dout_lo, p_w2h, p_w2l, b2,
        nullptr, nullptr, nullptr, nullptr, act_hi, act_lo, 1024, 0, 1);

    // 7: GEMM3a (igate)  out = sigmoid([iQ,h] @ Wg[:, :D] + bg[:D]) * iQ
    gemm_split_kernel<<<ggrid, THREADS, SMEM_GEMM_TOTAL>>>(
        iQ, act_hi, act_lo, p_wgh, p_wgl, bg,
        iQ, nullptr, nullptr, out, nullptr, nullptr, 2048, 16, 2);

    // 8: GEMM3b (fgate)  out += sigmoid([iQ,h] @ Wg[:, D:] + bg[D:]) * h
    gemm_split_kernel<<<ggrid, THREADS, SMEM_GEMM_TOTAL>>>(
        iQ, act_hi, act_lo, p_wgh + (size_t)1024 * 2048, p_wgl + (size_t)1024 * 2048,
        bg + 1024, nullptr, act_hi, act_lo, out, nullptr, nullptr, 2048, 16, 3);
}

// round 16
// speedup vs baseline: 1.0666x; 1.0666x over previous
#include <cuda_runtime.h>
#include <cuda_bf16.h>
#include <cstdint>

// ============================================================================
// Problem constants
// ============================================================================
static constexpr int BB = 4;
static constexpr int SS_ = 4096;
static constexpr int DD = 1024;
static constexpr int MTOT = BB * SS_;            // 16384
static constexpr int NCHUNK_S = 32;
static constexpr int LCHUNK_S = SS_ / NCHUNK_S;  // 128
static constexpr size_t PLANE = (size_t)MTOT * DD;   // elements per bf16 plane

// GEMM tiling: CTA 128x128, K-chunk 64, 256 threads, 3-stage pipeline (R12 base)
static constexpr int BM = 128, BN = 128, BK = 64;
static constexpr int THREADS = 256;
static constexpr int A_TILE = BM * BK * 2;       // 16 KB per plane
static constexpr int B_TILE = BN * BK * 2;       // 16 KB per plane
static constexpr int STAGE_BYTES = 2 * A_TILE + 2 * B_TILE;   // 64 KB
static constexpr int STAGES = 3;
static constexpr int SMEM_GEMM_TOTAL = STAGES * STAGE_BYTES;  // 192 KB

// ============================================================================
// Device scratch — 88.5 MiB total (single 128 MiB granule; passed R10/12/13)
// ============================================================================
__device__ __nv_bfloat16 g_act[2 * PLANE];                      // 64 MiB
__device__ __nv_bfloat16 g_w1t_hi[(size_t)DD * DD];             // 2 MiB
__device__ __nv_bfloat16 g_w1t_lo[(size_t)DD * DD];
__device__ __nv_bfloat16 g_w2t_hi[(size_t)DD * DD];
__device__ __nv_bfloat16 g_w2t_lo[(size_t)DD * DD];
__device__ __nv_bfloat16 g_wgt_hi[(size_t)2 * DD * 2 * DD];     // 8 MiB
__device__ __nv_bfloat16 g_wgt_lo[(size_t)2 * DD * 2 * DD];     // 8 MiB
__device__ float         g_part[BB * NCHUNK_S * DD];            // 0.5 MiB

// ============================================================================
// PTX helpers (sm_80-era: valid on plain sm_100 target)
// ============================================================================
__device__ __forceinline__ uint32_t smem_to_u32(const void* smem_ptr) {
    uint32_t addr;
    asm("{ .reg .u64 tmp; cvta.to.shared.u64 tmp, %1; cvt.u32.u64 %0, tmp; }"
        : "=r"(addr) : "l"(smem_ptr));
    return addr;
}

__device__ __forceinline__ void cp_async16(uint32_t dst, const void* src) {
    asm volatile("cp.async.cg.shared.global [%0], [%1], 16;" :: "r"(dst), "l"(src));
}
#define CP_COMMIT() asm volatile("cp.async.commit_group;" ::: "memory")
#define CP_WAIT(n)  asm volatile("cp.async.wait_group %0;" :: "n"(n) : "memory")

__device__ __forceinline__ void ldsm_x4(uint32_t* r, uint32_t addr) {
    asm volatile("ldmatrix.sync.aligned.m8n8.x4.shared.b16 {%0,%1,%2,%3}, [%4];"
                 : "=r"(r[0]), "=r"(r[1]), "=r"(r[2]), "=r"(r[3]) : "r"(addr));
}

__device__ __forceinline__ void mma_16816(float* d, const uint32_t* a,
                                          uint32_t b0, uint32_t b1) {
    asm volatile(
        "mma.sync.aligned.m16n8k16.row.col.f32.bf16.bf16.f32 "
        "{%0,%1,%2,%3}, {%4,%5,%6,%7}, {%8,%9}, {%0,%1,%2,%3};"
        : "+f"(d[0]), "+f"(d[1]), "+f"(d[2]), "+f"(d[3])
        : "r"(a[0]), "r"(a[1]), "r"(a[2]), "r"(a[3]), "r"(b0), "r"(b1));
}

__device__ __forceinline__ uint32_t pack_hi2(float x, float y) {
    __nv_bfloat16 hx = __float2bfloat16(x), hy = __float2bfloat16(y);
    return (uint32_t)__bfloat16_as_ushort(hx) |
           ((uint32_t)__bfloat16_as_ushort(hy) << 16);
}
__device__ __forceinline__ uint32_t pack_lo2(float x, float y) {
    __nv_bfloat16 hx = __float2bfloat16(x), hy = __float2bfloat16(y);
    __nv_bfloat16 lx = __float2bfloat16(x - __bfloat162float(hx));
    __nv_bfloat16 ly = __float2bfloat16(y - __bfloat162float(hy));
    return (uint32_t)__bfloat16_as_ushort(lx) |
           ((uint32_t)__bfloat16_as_ushort(ly) << 16);
}
__device__ __forceinline__ float2 unpack_bf16x2(uint32_t u) {
    float2 r;
    r.x = __bfloat162float(__ushort_as_bfloat16((unsigned short)(u & 0xFFFF)));
    r.y = __bfloat162float(__ushort_as_bfloat16((unsigned short)(u >> 16)));
    return r;
}

// ============================================================================
// Fused weight transpose + hi/lo split for ALL weights (one launch).
// ============================================================================
__global__ void transpose_all_kernel(const float* __restrict__ W1,
                                     const float* __restrict__ W2,
                                     const float* __restrict__ Wg) {
    const int z = blockIdx.z;
    const float* W; __nv_bfloat16 *Th, *Tl; int Kdim, N;
    if (z == 0)      { W = W1; Th = g_w1t_hi; Tl = g_w1t_lo; Kdim = 1024; N = 1024; }
    else if (z == 1) { W = W2; Th = g_w2t_hi; Tl = g_w2t_lo; Kdim = 1024; N = 1024; }
    else             { W = Wg; Th = g_wgt_hi; Tl = g_wgt_lo; Kdim = 2048; N = 2048; }
    const int n0 = blockIdx.x * 32, k0 = blockIdx.y * 32;
    if (n0 >= N || k0 >= Kdim) return;
    __shared__ float t[32][33];
    const int tx = threadIdx.x, ty = threadIdx.y;
#pragma unroll
    for (int i = 0; i < 32; i += 8)
        t[ty + i][tx] = W[(size_t)(k0 + ty + i) * N + (n0 + tx)];
    __syncthreads();
#pragma unroll
    for (int i = 0; i < 32; i += 8) {
        float f = t[tx][ty + i];
        __nv_bfloat16 h = __float2bfloat16(f);
        __nv_bfloat16 q = __float2bfloat16(f - __bfloat162float(h));
        size_t o = (size_t)(n0 + ty + i) * Kdim + (k0 + tx);
        Th[o] = h; Tl[o] = q;
    }
}

// ============================================================================
// Prefix-mean, 2 passes: part sums, then fused (scan + avg) -> planes in g_act
// ============================================================================
__global__ void cumsum_part_kernel(const float* __restrict__ iV) {
    const int b = blockIdx.z, dg = blockIdx.y, c = blockIdx.x;
    const int d = dg * 256 + threadIdx.x;
    const float* p = iV + ((size_t)b * SS_ + (size_t)c * LCHUNK_S) * DD + d;
    float acc = 0.f;
#pragma unroll 4
    for (int s = 0; s < LCHUNK_S; s++) acc += p[(size_t)s * DD];
    g_part[(b * NCHUNK_S + c) * DD + d] = acc;
}

__global__ void cumsum_avg_kernel(const float* __restrict__ iV) {
    const int b = blockIdx.z, dg = blockIdx.y, c = blockIdx.x;
    const int d = dg * 256 + threadIdx.x;
    // fused exclusive scan over chunk partials
    float run = 0.f;
    for (int cc = 0; cc < c; cc++)
        run += g_part[(b * NCHUNK_S + cc) * DD + d];
    const size_t base = ((size_t)b * SS_ + (size_t)c * LCHUNK_S) * DD + d;
    const float* p = iV + base;
#pragma unroll 4
    for (int s = 0; s < LCHUNK_S; s++) {
        run += p[(size_t)s * DD];
        float a = run / (float)(c * LCHUNK_S + s + 1);
        __nv_bfloat16 h = __float2bfloat16(a);
        __nv_bfloat16 l = __float2bfloat16(a - __bfloat162float(h));
        g_act[base + (size_t)s * DD] = h;
        g_act[PLANE + base + (size_t)s * DD] = l;
    }
}

// ============================================================================
// Split-bf16 GEMM, CTA 128x128, 256 threads, 3-stage pipeline.
//   Product-major MMA ordering: per ks, all AhiBhi, then all AhiBlo, then all
//   AloBhi — re-write distance per accumulator = 16 issues (breaks the HMMA
//   dependency chain that bound R12 at ~53% of tensor peak).
//   modes: 0 relu->planes; 1 plain->planes; 2 outf = sig(x)*epi_f32;
//          3 outf += sig(x)*(epi_hi+epi_lo)
// ============================================================================
__global__ void __launch_bounds__(THREADS, 1) gemm_split_kernel(
    const float* __restrict__ Af32,
    const __nv_bfloat16* __restrict__ Ahi, const __nv_bfloat16* __restrict__ Alo,
    const __nv_bfloat16* __restrict__ Bh,  const __nv_bfloat16* __restrict__ Bl,
    const float* __restrict__ bias,
    const float* __restrict__ epi_f32,
    const __nv_bfloat16* __restrict__ epi_hi, const __nv_bfloat16* __restrict__ epi_lo,
    float* __restrict__ out_f32,
    __nv_bfloat16* __restrict__ out_hi, __nv_bfloat16* __restrict__ out_lo,
    int K, int nf32, int mode)
{
    extern __shared__ __align__(16) char smem[];
    const uint32_t sbase = smem_to_u32(smem);
    const int tid = threadIdx.x;
    const int w = tid >> 5, l = tid & 31;
    const int wm = w & 3, wn = w >> 2;           // warp tile: rows wm*32, cols wn*64
    const int mbase = blockIdx.x * BM, nbase = blockIdx.y * BN;
    const int NC = K >> 6;

    const int ar = tid >> 3, ac = tid & 7;       // A f32 loader indices

    float acc[2][8][4];
#pragma unroll
    for (int a = 0; a < 2; a++)
#pragma unroll
        for (int b = 0; b < 8; b++)
#pragma unroll
            for (int c = 0; c < 4; c++) acc[a][b][c] = 0.f;

    float4 areg[4][2];

    auto lda_f32 = [&](int ch) {
        const float* s = Af32 + (size_t)mbase * 1024 + (ch << 6);
#pragma unroll
        for (int p = 0; p < 4; p++) {
            const float* rp = s + (size_t)(ar + p * 32) * 1024 + ac * 8;
            areg[p][0] = *(const float4*)(rp);
            areg[p][1] = *(const float4*)(rp + 4);
        }
    };
    auto sts_a = [&](int ch) {
        const uint32_t abuf = (uint32_t)((ch % STAGES) * STAGE_BYTES);
#pragma unroll
        for (int p = 0; p < 4; p++) {
            const int r = ar + p * 32;
            const uint32_t off = (uint32_t)(r * 128 + ((ac ^ (r & 7)) << 4));
            float4 v0 = areg[p][0], v1 = areg[p][1];
            uint4 hv, lv;
            hv.x = pack_hi2(v0.x, v0.y); hv.y = pack_hi2(v0.z, v0.w);
            hv.z = pack_hi2(v1.x, v1.y); hv.w = pack_hi2(v1.z, v1.w);
            lv.x = pack_lo2(v0.x, v0.y); lv.y = pack_lo2(v0.z, v0.w);
            lv.z = pack_lo2(v1.x, v1.y); lv.w = pack_lo2(v1.z, v1.w);
            *(uint4*)(smem + abuf + off) = hv;
            *(uint4*)(smem + abuf + A_TILE + off) = lv;
        }
    };
    auto lda_planes = [&](int ch) {
        const uint32_t abuf = sbase + (uint32_t)((ch % STAGES) * STAGE_BYTES);
        const int kk = (ch - nf32) << 6;
#pragma unroll
        for (int i = 0; i < 4; i++) {
            const int cid = tid + i * THREADS;
            const int r = cid >> 3, c = cid & 7;
            const uint32_t off = (uint32_t)(r * 128 + ((c ^ (r & 7)) << 4));
            const size_t gsrc = (size_t)(mbase + r) * 1024 + kk + c * 8;
            cp_async16(abuf + off, Ahi + gsrc);
            cp_async16(abuf + A_TILE + off, Alo + gsrc);
        }
    };
    auto ldb = [&](int ch) {
        const uint32_t bbuf = sbase + (uint32_t)((ch % STAGES) * STAGE_BYTES)
                              + 2 * A_TILE;
        const int kk = ch << 6;
#pragma unroll
        for (int i = 0; i < 4; i++) {
            const int cid = tid + i * THREADS;
            const int r = cid >> 3, c = cid & 7;
            const uint32_t off = (uint32_t)(r * 128 + ((c ^ (r & 7)) << 4));
            const size_t gsrc = (size_t)(nbase + r) * K + kk + c * 8;
            cp_async16(bbuf + off, Bh + gsrc);
            cp_async16(bbuf + B_TILE + off, Bl + gsrc);
        }
    };
    auto mma_chunk = [&](int ch) {
        const uint32_t sb = sbase + (uint32_t)((ch % STAGES) * STAGE_BYTES);
        const uint32_t ahiB = sb, aloB = sb + A_TILE;
        const uint32_t bhiB = sb + 2 * A_TILE, bloB = bhiB + B_TILE;
#pragma unroll
        for (int ks = 0; ks < 4; ks++) {
            const int cc = ks * 2 + (l >> 4);
            uint32_t ah[2][4], al[2][4], bh[4][4], bl[4][4];
#pragma unroll
            for (int mt = 0; mt < 2; mt++) {
                const int row = wm * 32 + mt * 16 + (l & 15);
                const uint32_t off = (uint32_t)(row * 128 + ((cc ^ (row & 7)) << 4));
                ldsm_x4(ah[mt], ahiB + off);
                ldsm_x4(al[mt], aloB + off);
            }
#pragma unroll
            for (int bt = 0; bt < 4; bt++) {
                const int row = wn * 64 + bt * 16 + (l & 15);
                const uint32_t off = (uint32_t)(row * 128 + ((cc ^ (row & 7)) << 4));
                ldsm_x4(bh[bt], bhiB + off);
                ldsm_x4(bl[bt], bloB + off);
            }
            // product 1: Ahi * Bhi  (16 independent MMAs)
#pragma unroll
            for (int mt = 0; mt < 2; mt++)
#pragma unroll
                for (int bt = 0; bt < 4; bt++) {
                    mma_16816(acc[mt][bt * 2],     ah[mt], bh[bt][0], bh[bt][2]);
                    mma_16816(acc[mt][bt * 2 + 1], ah[mt], bh[bt][1], bh[bt][3]);
                }
            // product 2: Ahi * Blo
#pragma unroll
            for (int mt = 0; mt < 2; mt++)
#pragma unroll
                for (int bt = 0; bt < 4; bt++) {
                    mma_16816(acc[mt][bt * 2],     ah[mt], bl[bt][0], bl[bt][2]);
                    mma_16816(acc[mt][bt * 2 + 1], ah[mt], bl[bt][1], bl[bt][3]);
                }
            // product 3: Alo * Bhi
#pragma unroll
            for (int mt = 0; mt < 2; mt++)
#pragma unroll
                for (int bt = 0; bt < 4; bt++) {
                    mma_16816(acc[mt][bt * 2],     al[mt], bh[bt][0], bh[bt][2]);
                    mma_16816(acc[mt][bt * 2 + 1], al[mt], bh[bt][1], bh[bt][3]);
                }
        }
    };

    // ---- prologue: stages 0 and 1 ----
#pragma unroll
    for (int s = 0; s < STAGES - 1; s++) {
        const bool f32c = (s < nf32);
        if (f32c) lda_f32(s); else lda_planes(s);
        ldb(s);
        CP_COMMIT();
        if (f32c) sts_a(s);
    }

    // ---- main loop: wait_group(2) keeps 2 stages in flight ----
    for (int ch = 0; ch < NC; ch++) {
        const int pf = ch + STAGES - 1;
        const bool pf_valid = (pf < NC);
        const bool pf_f32 = pf_valid && (pf < nf32);
        if (pf_valid) {
            if (pf_f32) lda_f32(pf); else lda_planes(pf);
            ldb(pf);
        }
        CP_COMMIT();
        CP_WAIT(2);
        __syncthreads();
        mma_chunk(ch);
        if (pf_f32) sts_a(pf);
        __syncthreads();
    }

    // ---- epilogue ----
    const int quad = l >> 2, qid = l & 3;
#pragma unroll
    for (int mt = 0; mt < 2; mt++) {
#pragma unroll
        for (int nt = 0; nt < 8; nt++) {
            const int col = nbase + wn * 64 + nt * 8 + qid * 2;
            const float2 bb = *(const float2*)(bias + col);
#pragma unroll
            for (int h2 = 0; h2 < 2; h2++) {
                const int r = mbase + wm * 32 + mt * 16 + quad + h2 * 8;
                float x = acc[mt][nt][h2 * 2 + 0] + bb.x;
                float y = acc[mt][nt][h2 * 2 + 1] + bb.y;
                const size_t idx = (size_t)r * 1024 + col;
                if (mode == 0 || mode == 1) {
                    if (mode == 0) { x = x > 0.f ? x : 0.f; y = y > 0.f ? y : 0.f; }
                    *(uint32_t*)(out_hi + idx) = pack_hi2(x, y);
                    *(uint32_t*)(out_lo + idx) = pack_lo2(x, y);
                } else {
                    float sx = 1.f / (1.f + __expf(-x));
                    float sy = 1.f / (1.f + __expf(-y));
                    if (mode == 2) {
                        const float2 e = *(const float2*)(epi_f32 + idx);
                        float2 v; v.x = sx * e.x; v.y = sy * e.y;
                        *(float2*)(out_f32 + idx) = v;
                    } else {
                        float2 eh = unpack_bf16x2(*(const uint32_t*)(epi_hi + idx));
                        float2 el = unpack_bf16x2(*(const uint32_t*)(epi_lo + idx));
                        float2 o = *(const float2*)(out_f32 + idx);
                        o.x += sx * (eh.x + el.x);
                        o.y += sy * (eh.y + el.y);
                        *(float2*)(out_f32 + idx) = o;
                    }
                }
            }
        }
    }
}

// ============================================================================
// Launch — order puts GEMM1 at launch #4 (ncu capture position):
//   1 transpose_all, 2 part, 3 avg(fused scan), 4 g1, 5 g2, 6 g3a, 7 g3b
// Plane plan: avg planes->g_act ; g1: g_act->d_out planes (u)
//   g2: d_out planes -> g_act planes (h)
//   g3a: A=[iQ f32, h planes]; out = sig(.)*iQ -> d_out fp32
//   g3b: same A; out += sig(.)*h
// ============================================================================
extern "C" void kernel_launch(void* const* d_in, const int* in_sizes, int n_in,
                              void* d_out, int out_size) {
    const float* iQ = (const float*)d_in[0];
    const float* iV = (const float*)d_in[1];
    const float* W1 = (const float*)d_in[2];
    const float* b1 = (const float*)d_in[3];
    const float* W2 = (const float*)d_in[4];
    const float* b2 = (const float*)d_in[5];
    const float* Wg = (const float*)d_in[6];
    const float* bg = (const float*)d_in[7];
    float* out = (float*)d_out;

    cudaFuncSetAttribute(gemm_split_kernel,
                         cudaFuncAttributeMaxDynamicSharedMemorySize,
                         SMEM_GEMM_TOTAL);

    __nv_bfloat16 *p_act = nullptr;
    __nv_bfloat16 *p_w1h = nullptr, *p_w1l = nullptr;
    __nv_bfloat16 *p_w2h = nullptr, *p_w2l = nullptr;
    __nv_bfloat16 *p_wgh = nullptr, *p_wgl = nullptr;
    cudaGetSymbolAddress((void**)&p_act, g_act);
    cudaGetSymbolAddress((void**)&p_w1h, g_w1t_hi);
    cudaGetSymbolAddress((void**)&p_w1l, g_w1t_lo);
    cudaGetSymbolAddress((void**)&p_w2h, g_w2t_hi);
    cudaGetSymbolAddress((void**)&p_w2l, g_w2t_lo);
    cudaGetSymbolAddress((void**)&p_wgh, g_wgt_hi);
    cudaGetSymbolAddress((void**)&p_wgl, g_wgt_lo);
    __nv_bfloat16* act_hi = p_act;
    __nv_bfloat16* act_lo = p_act + PLANE;
    __nv_bfloat16* dout_hi = (__nv_bfloat16*)out;
    __nv_bfloat16* dout_lo = (__nv_bfloat16*)out + PLANE;

    // 1: all weight transposes
    transpose_all_kernel<<<dim3(64, 64, 3), dim3(32, 8)>>>(W1, W2, Wg);

    // 2-3: prefix-mean (part, fused scan+avg)
    cumsum_part_kernel<<<dim3(NCHUNK_S, DD / 256, BB), 256>>>(iV);
    cumsum_avg_kernel<<<dim3(NCHUNK_S, DD / 256, BB), 256>>>(iV);

    const dim3 ggrid(MTOT / BM, 1024 / BN);   // (128, 8)

    // 4: GEMM1  u = relu(avg @ W1 + b1)    g_act planes -> d_out planes
    gemm_split_kernel<<<ggrid, THREADS, SMEM_GEMM_TOTAL>>>(
        nullptr, act_hi, act_lo, p_w1h, p_w1l, b1,
        nullptr, nullptr, nullptr, nullptr, dout_hi, dout_lo, 1024, 0, 0);

    // 5: GEMM2  h = u @ W2 + b2            d_out planes -> g_act planes
    gemm_split_kernel<<<ggrid, THREADS, SMEM_GEMM_TOTAL>>>(
        nullptr, dout_hi, dout_lo, p_w2h, p_w2l, b2,
        nullptr, nullptr, nullptr, nullptr, act_hi, act_lo, 1024, 0, 1);

    // 6: GEMM3a (igate)  out = sigmoid([iQ,h] @ Wg[:, :D] + bg[:D]) * iQ
    gemm_split_kernel<<<ggrid, THREADS, SMEM_GEMM_TOTAL>>>(
        iQ, act_hi, act_lo, p_wgh, p_wgl, bg,
        iQ, nullptr, nullptr, out, nullptr, nullptr, 2048, 16, 2);

    // 7: GEMM3b (fgate)  out += sigmoid([iQ,h] @ Wg[:, D:] + bg[D:]) * h
    gemm_split_kernel<<<ggrid, THREADS, SMEM_GEMM_TOTAL>>>(
        iQ, act_hi, act_lo, p_wgh + (size_t)1024 * 2048, p_wgl + (size_t)1024 * 2048,
        bg + 1024, nullptr, act_hi, act_lo, out, nullptr, nullptr, 2048, 16, 3);
}

// round 17
// speedup vs baseline: 1.2495x; 1.1714x over previous
#include <cuda_runtime.h>
#include <cuda_bf16.h>
#include <cstdint>

// ============================================================================
// Problem constants
// ============================================================================
static constexpr int BB = 4;
static constexpr int SS_ = 4096;
static constexpr int DD = 1024;
static constexpr int MTOT = BB * SS_;            // 16384
static constexpr int NCHUNK_S = 32;
static constexpr int LCHUNK_S = SS_ / NCHUNK_S;  // 128
static constexpr size_t PLANE = (size_t)MTOT * DD;   // elements per bf16 plane

// GEMM tiling: CTA 64x128, K-chunk 64, 256 threads, 2-stage, 2 CTAs/SM
static constexpr int BM = 64, BN = 128, BK = 64;
static constexpr int THREADS = 256;
static constexpr int A_TILE = BM * BK * 2;       // 8 KB per plane
static constexpr int B_TILE = BN * BK * 2;       // 16 KB per plane
static constexpr int STAGE_BYTES = 2 * A_TILE + 2 * B_TILE;   // 48 KB
static constexpr int STAGES = 2;
static constexpr int SMEM_GEMM_TOTAL = STAGES * STAGE_BYTES;  // 96 KB (x2 CTAs = 192)

// ============================================================================
// Device scratch — 88.5 MiB total (single 128 MiB granule; passed R10-R16)
// ============================================================================
__device__ __nv_bfloat16 g_act[2 * PLANE];                      // 64 MiB
__device__ __nv_bfloat16 g_w1t_hi[(size_t)DD * DD];             // 2 MiB
__device__ __nv_bfloat16 g_w1t_lo[(size_t)DD * DD];
__device__ __nv_bfloat16 g_w2t_hi[(size_t)DD * DD];
__device__ __nv_bfloat16 g_w2t_lo[(size_t)DD * DD];
__device__ __nv_bfloat16 g_wgt_hi[(size_t)2 * DD * 2 * DD];     // 8 MiB
__device__ __nv_bfloat16 g_wgt_lo[(size_t)2 * DD * 2 * DD];     // 8 MiB
__device__ float         g_part[BB * NCHUNK_S * DD];            // 0.5 MiB

// ============================================================================
// PTX helpers (sm_80-era: valid on plain sm_100 target)
// ============================================================================
__device__ __forceinline__ uint32_t smem_to_u32(const void* smem_ptr) {
    uint32_t addr;
    asm("{ .reg .u64 tmp; cvta.to.shared.u64 tmp, %1; cvt.u32.u64 %0, tmp; }"
        : "=r"(addr) : "l"(smem_ptr));
    return addr;
}

__device__ __forceinline__ void cp_async16(uint32_t dst, const void* src) {
    asm volatile("cp.async.cg.shared.global [%0], [%1], 16;" :: "r"(dst), "l"(src));
}
#define CP_COMMIT() asm volatile("cp.async.commit_group;" ::: "memory")
#define CP_WAIT(n)  asm volatile("cp.async.wait_group %0;" :: "n"(n) : "memory")

__device__ __forceinline__ void ldsm_x4(uint32_t* r, uint32_t addr) {
    asm volatile("ldmatrix.sync.aligned.m8n8.x4.shared.b16 {%0,%1,%2,%3}, [%4];"
                 : "=r"(r[0]), "=r"(r[1]), "=r"(r[2]), "=r"(r[3]) : "r"(addr));
}

__device__ __forceinline__ void mma_16816(float* d, const uint32_t* a,
                                          uint32_t b0, uint32_t b1) {
    asm volatile(
        "mma.sync.aligned.m16n8k16.row.col.f32.bf16.bf16.f32 "
        "{%0,%1,%2,%3}, {%4,%5,%6,%7}, {%8,%9}, {%0,%1,%2,%3};"
        : "+f"(d[0]), "+f"(d[1]), "+f"(d[2]), "+f"(d[3])
        : "r"(a[0]), "r"(a[1]), "r"(a[2]), "r"(a[3]), "r"(b0), "r"(b1));
}

__device__ __forceinline__ uint32_t pack_hi2(float x, float y) {
    __nv_bfloat16 hx = __float2bfloat16(x), hy = __float2bfloat16(y);
    return (uint32_t)__bfloat16_as_ushort(hx) |
           ((uint32_t)__bfloat16_as_ushort(hy) << 16);
}
__device__ __forceinline__ uint32_t pack_lo2(float x, float y) {
    __nv_bfloat16 hx = __float2bfloat16(x), hy = __float2bfloat16(y);
    __nv_bfloat16 lx = __float2bfloat16(x - __bfloat162float(hx));
    __nv_bfloat16 ly = __float2bfloat16(y - __bfloat162float(hy));
    return (uint32_t)__bfloat16_as_ushort(lx) |
           ((uint32_t)__bfloat16_as_ushort(ly) << 16);
}
__device__ __forceinline__ float2 unpack_bf16x2(uint32_t u) {
    float2 r;
    r.x = __bfloat162float(__ushort_as_bfloat16((unsigned short)(u & 0xFFFF)));
    r.y = __bfloat162float(__ushort_as_bfloat16((unsigned short)(u >> 16)));
    return r;
}

// ============================================================================
// Fused weight transpose + hi/lo split for ALL weights (one launch).
// ============================================================================
__global__ void transpose_all_kernel(const float* __restrict__ W1,
                                     const float* __restrict__ W2,
                                     const float* __restrict__ Wg) {
    const int z = blockIdx.z;
    const float* W; __nv_bfloat16 *Th, *Tl; int Kdim, N;
    if (z == 0)      { W = W1; Th = g_w1t_hi; Tl = g_w1t_lo; Kdim = 1024; N = 1024; }
    else if (z == 1) { W = W2; Th = g_w2t_hi; Tl = g_w2t_lo; Kdim = 1024; N = 1024; }
    else             { W = Wg; Th = g_wgt_hi; Tl = g_wgt_lo; Kdim = 2048; N = 2048; }
    const int n0 = blockIdx.x * 32, k0 = blockIdx.y * 32;
    if (n0 >= N || k0 >= Kdim) return;
    __shared__ float t[32][33];
    const int tx = threadIdx.x, ty = threadIdx.y;
#pragma unroll
    for (int i = 0; i < 32; i += 8)
        t[ty + i][tx] = W[(size_t)(k0 + ty + i) * N + (n0 + tx)];
    __syncthreads();
#pragma unroll
    for (int i = 0; i < 32; i += 8) {
        float f = t[tx][ty + i];
        __nv_bfloat16 h = __float2bfloat16(f);
        __nv_bfloat16 q = __float2bfloat16(f - __bfloat162float(h));
        size_t o = (size_t)(n0 + ty + i) * Kdim + (k0 + tx);
        Th[o] = h; Tl[o] = q;
    }
}

// ============================================================================
// Prefix-mean, 2 passes: part sums, then fused (scan + avg) -> planes in g_act
// ============================================================================
__global__ void cumsum_part_kernel(const float* __restrict__ iV) {
    const int b = blockIdx.z, dg = blockIdx.y, c = blockIdx.x;
    const int d = dg * 256 + threadIdx.x;
    const float* p = iV + ((size_t)b * SS_ + (size_t)c * LCHUNK_S) * DD + d;
    float acc = 0.f;
#pragma unroll 4
    for (int s = 0; s < LCHUNK_S; s++) acc += p[(size_t)s * DD];
    g_part[(b * NCHUNK_S + c) * DD + d] = acc;
}

__global__ void cumsum_avg_kernel(const float* __restrict__ iV) {
    const int b = blockIdx.z, dg = blockIdx.y, c = blockIdx.x;
    const int d = dg * 256 + threadIdx.x;
    float run = 0.f;
    for (int cc = 0; cc < c; cc++)
        run += g_part[(b * NCHUNK_S + cc) * DD + d];
    const size_t base = ((size_t)b * SS_ + (size_t)c * LCHUNK_S) * DD + d;
    const float* p = iV + base;
#pragma unroll 4
    for (int s = 0; s < LCHUNK_S; s++) {
        run += p[(size_t)s * DD];
        float a = run / (float)(c * LCHUNK_S + s + 1);
        __nv_bfloat16 h = __float2bfloat16(a);
        __nv_bfloat16 l = __float2bfloat16(a - __bfloat162float(h));
        g_act[base + (size_t)s * DD] = h;
        g_act[PLANE + base + (size_t)s * DD] = l;
    }
}

// ============================================================================
// Split-bf16 GEMM, CTA 64x128, 256 threads (4x2 m-n warp grid is 2x4 here:
// wm = w&1 over 2x32 rows, wn = w>>1 over 4x32 cols), warp tile 32x32.
// 2 CTAs/SM (regs<=128, 96KB smem/CTA) for cross-CTA latency hiding.
// Per chunk: AhiBhi + AhiBlo + AloBhi (product-major).
// modes: 0 relu->planes; 1 plain->planes; 2 outf = sig(x)*epi_f32;
//        3 outf += sig(x)*(epi_hi+epi_lo)
// ============================================================================
__global__ void __launch_bounds__(THREADS, 2) gemm_split_kernel(
    const float* __restrict__ Af32,
    const __nv_bfloat16* __restrict__ Ahi, const __nv_bfloat16* __restrict__ Alo,
    const __nv_bfloat16* __restrict__ Bh,  const __nv_bfloat16* __restrict__ Bl,
    const float* __restrict__ bias,
    const float* __restrict__ epi_f32,
    const __nv_bfloat16* __restrict__ epi_hi, const __nv_bfloat16* __restrict__ epi_lo,
    float* __restrict__ out_f32,
    __nv_bfloat16* __restrict__ out_hi, __nv_bfloat16* __restrict__ out_lo,
    int K, int nf32, int mode)
{
    extern __shared__ __align__(16) char smem[];
    const uint32_t sbase = smem_to_u32(smem);
    const int tid = threadIdx.x;
    const int w = tid >> 5, l = tid & 31;
    const int wm = w & 1, wn = w >> 1;           // warp tile: rows wm*32, cols wn*32
    const int mbase = blockIdx.x * BM, nbase = blockIdx.y * BN;
    const int NC = K >> 6;

    const int ar = tid >> 3, ac = tid & 7;       // A f32 loader: rows ar+p*32

    float acc[2][4][4];
#pragma unroll
    for (int a = 0; a < 2; a++)
#pragma unroll
        for (int b = 0; b < 4; b++)
#pragma unroll
            for (int c = 0; c < 4; c++) acc[a][b][c] = 0.f;

    float4 areg[2][2];

    auto lda_f32 = [&](int ch) {
        const float* s = Af32 + (size_t)mbase * 1024 + (ch << 6);
#pragma unroll
        for (int p = 0; p < 2; p++) {
            const float* rp = s + (size_t)(ar + p * 32) * 1024 + ac * 8;
            areg[p][0] = *(const float4*)(rp);
            areg[p][1] = *(const float4*)(rp + 4);
        }
    };
    auto sts_a = [&](int ch) {
        const uint32_t abuf = (uint32_t)((ch & 1) * STAGE_BYTES);
#pragma unroll
        for (int p = 0; p < 2; p++) {
            const int r = ar + p * 32;
            const uint32_t off = (uint32_t)(r * 128 + ((ac ^ (r & 7)) << 4));
            float4 v0 = areg[p][0], v1 = areg[p][1];
            uint4 hv, lv;
            hv.x = pack_hi2(v0.x, v0.y); hv.y = pack_hi2(v0.z, v0.w);
            hv.z = pack_hi2(v1.x, v1.y); hv.w = pack_hi2(v1.z, v1.w);
            lv.x = pack_lo2(v0.x, v0.y); lv.y = pack_lo2(v0.z, v0.w);
            lv.z = pack_lo2(v1.x, v1.y); lv.w = pack_lo2(v1.z, v1.w);
            *(uint4*)(smem + abuf + off) = hv;
            *(uint4*)(smem + abuf + A_TILE + off) = lv;
        }
    };
    auto lda_planes = [&](int ch) {
        const uint32_t abuf = sbase + (uint32_t)((ch & 1) * STAGE_BYTES);
        const int kk = (ch - nf32) << 6;
#pragma unroll
        for (int i = 0; i < 2; i++) {
            const int cid = tid + i * THREADS;   // 512 cells
            const int r = cid >> 3, c = cid & 7;
            const uint32_t off = (uint32_t)(r * 128 + ((c ^ (r & 7)) << 4));
            const size_t gsrc = (size_t)(mbase + r) * 1024 + kk + c * 8;
            cp_async16(abuf + off, Ahi + gsrc);
            cp_async16(abuf + A_TILE + off, Alo + gsrc);
        }
    };
    auto ldb = [&](int ch) {
        const uint32_t bbuf = sbase + (uint32_t)((ch & 1) * STAGE_BYTES)
                              + 2 * A_TILE;
        const int kk = ch << 6;
#pragma unroll
        for (int i = 0; i < 4; i++) {
            const int cid = tid + i * THREADS;   // 1024 cells
            const int r = cid >> 3, c = cid & 7;
            const uint32_t off = (uint32_t)(r * 128 + ((c ^ (r & 7)) << 4));
            const size_t gsrc = (size_t)(nbase + r) * K + kk + c * 8;
            cp_async16(bbuf + off, Bh + gsrc);
            cp_async16(bbuf + B_TILE + off, Bl + gsrc);
        }
    };
    auto mma_chunk = [&](int ch) {
        const uint32_t sb = sbase + (uint32_t)((ch & 1) * STAGE_BYTES);
        const uint32_t ahiB = sb, aloB = sb + A_TILE;
        const uint32_t bhiB = sb + 2 * A_TILE, bloB = bhiB + B_TILE;
#pragma unroll
        for (int ks = 0; ks < 4; ks++) {
            const int cc = ks * 2 + (l >> 4);
            uint32_t ah[2][4], al[2][4], bh[2][4], bl[2][4];
#pragma unroll
            for (int mt = 0; mt < 2; mt++) {
                const int row = wm * 32 + mt * 16 + (l & 15);
                const uint32_t off = (uint32_t)(row * 128 + ((cc ^ (row & 7)) << 4));
                ldsm_x4(ah[mt], ahiB + off);
                ldsm_x4(al[mt], aloB + off);
            }
#pragma unroll
            for (int bt = 0; bt < 2; bt++) {
                const int row = wn * 32 + bt * 16 + (l & 15);
                const uint32_t off = (uint32_t)(row * 128 + ((cc ^ (row & 7)) << 4));
                ldsm_x4(bh[bt], bhiB + off);
                ldsm_x4(bl[bt], bloB + off);
            }
            // product 1: Ahi * Bhi
#pragma unroll
            for (int mt = 0; mt < 2; mt++)
#pragma unroll
                for (int bt = 0; bt < 2; bt++) {
                    mma_16816(acc[mt][bt * 2],     ah[mt], bh[bt][0], bh[bt][2]);
                    mma_16816(acc[mt][bt * 2 + 1], ah[mt], bh[bt][1], bh[bt][3]);
                }
            // product 2: Ahi * Blo
#pragma unroll
            for (int mt = 0; mt < 2; mt++)
#pragma unroll
                for (int bt = 0; bt < 2; bt++) {
                    mma_16816(acc[mt][bt * 2],     ah[mt], bl[bt][0], bl[bt][2]);
                    mma_16816(acc[mt][bt * 2 + 1], ah[mt], bl[bt][1], bl[bt][3]);
                }
            // product 3: Alo * Bhi
#pragma unroll
            for (int mt = 0; mt < 2; mt++)
#pragma unroll
                for (int bt = 0; bt < 2; bt++) {
                    mma_16816(acc[mt][bt * 2],     al[mt], bh[bt][0], bh[bt][2]);
                    mma_16816(acc[mt][bt * 2 + 1], al[mt], bh[bt][1], bh[bt][3]);
                }
        }
    };

    // ---- prologue: stage 0 ----
    {
        const bool f32c = (0 < nf32);
        if (f32c) lda_f32(0); else lda_planes(0);
        ldb(0);
        CP_COMMIT();
        if (f32c) sts_a(0);
    }

    // ---- main loop ----
    for (int ch = 0; ch < NC; ch++) {
        const int pf = ch + 1;
        const bool pf_valid = (pf < NC);
        const bool pf_f32 = pf_valid && (pf < nf32);
        if (pf_valid) {
            if (pf_f32) lda_f32(pf); else lda_planes(pf);
            ldb(pf);
        }
        CP_COMMIT();
        CP_WAIT(1);
        __syncthreads();
        if (pf_f32) sts_a(pf);      // writes stage pf&1; mma reads ch&1
        mma_chunk(ch);
        __syncthreads();
    }

    // ---- epilogue ----
    const int quad = l >> 2, qid = l & 3;
#pragma unroll
    for (int mt = 0; mt < 2; mt++) {
#pragma unroll
        for (int j = 0; j < 4; j++) {
            const int col = nbase + wn * 32 + (j >> 1) * 16 + (j & 1) * 8 + qid * 2;
            const float2 bb = *(const float2*)(bias + col);
#pragma unroll
            for (int h2 = 0; h2 < 2; h2++) {
                const int r = mbase + wm * 32 + mt * 16 + quad + h2 * 8;
                float x = acc[mt][j][h2 * 2 + 0] + bb.x;
                float y = acc[mt][j][h2 * 2 + 1] + bb.y;
                const size_t idx = (size_t)r * 1024 + col;
                if (mode == 0 || mode == 1) {
                    if (mode == 0) { x = x > 0.f ? x : 0.f; y = y > 0.f ? y : 0.f; }
                    *(uint32_t*)(out_hi + idx) = pack_hi2(x, y);
                    *(uint32_t*)(out_lo + idx) = pack_lo2(x, y);
                } else {
                    float sx = 1.f / (1.f + __expf(-x));
                    float sy = 1.f / (1.f + __expf(-y));
                    if (mode == 2) {
                        const float2 e = *(const float2*)(epi_f32 + idx);
                        float2 v; v.x = sx * e.x; v.y = sy * e.y;
                        *(float2*)(out_f32 + idx) = v;
                    } else {
                        float2 eh = unpack_bf16x2(*(const uint32_t*)(epi_hi + idx));
                        float2 el = unpack_bf16x2(*(const uint32_t*)(epi_lo + idx));
                        float2 o = *(const float2*)(out_f32 + idx);
                        o.x += sx * (eh.x + el.x);
                        o.y += sy * (eh.y + el.y);
                        *(float2*)(out_f32 + idx) = o;
                    }
                }
            }
        }
    }
}

// ============================================================================
// Launch — order keeps GEMM1 at launch #4 (ncu capture position):
//   1 transpose_all, 2 part, 3 avg(fused scan), 4 g1, 5 g2, 6 g3a, 7 g3b
// ============================================================================
extern "C" void kernel_launch(void* const* d_in, const int* in_sizes, int n_in,
                              void* d_out, int out_size) {
    const float* iQ = (const float*)d_in[0];
    const float* iV = (const float*)d_in[1];
    const float* W1 = (const float*)d_in[2];
    const float* b1 = (const float*)d_in[3];
    const float* W2 = (const float*)d_in[4];
    const float* b2 = (const float*)d_in[5];
    const float* Wg = (const float*)d_in[6];
    const float* bg = (const float*)d_in[7];
    float* out = (float*)d_out;

    cudaFuncSetAttribute(gemm_split_kernel,
                         cudaFuncAttributeMaxDynamicSharedMemorySize,
                         SMEM_GEMM_TOTAL);

    __nv_bfloat16 *p_act = nullptr;
    __nv_bfloat16 *p_w1h = nullptr, *p_w1l = nullptr;
    __nv_bfloat16 *p_w2h = nullptr, *p_w2l = nullptr;
    __nv_bfloat16 *p_wgh = nullptr, *p_wgl = nullptr;
    cudaGetSymbolAddress((void**)&p_act, g_act);
    cudaGetSymbolAddress((void**)&p_w1h, g_w1t_hi);
    cudaGetSymbolAddress((void**)&p_w1l, g_w1t_lo);
    cudaGetSymbolAddress((void**)&p_w2h, g_w2t_hi);
    cudaGetSymbolAddress((void**)&p_w2l, g_w2t_lo);
    cudaGetSymbolAddress((void**)&p_wgh, g_wgt_hi);
    cudaGetSymbolAddress((void**)&p_wgl, g_wgt_lo);
    __nv_bfloat16* act_hi = p_act;
    __nv_bfloat16* act_lo = p_act + PLANE;
    __nv_bfloat16* dout_hi = (__nv_bfloat16*)out;
    __nv_bfloat16* dout_lo = (__nv_bfloat16*)out + PLANE;

    // 1: all weight transposes
    transpose_all_kernel<<<dim3(64, 64, 3), dim3(32, 8)>>>(W1, W2, Wg);

    // 2-3: prefix-mean (part, fused scan+avg)
    cumsum_part_kernel<<<dim3(NCHUNK_S, DD / 256, BB), 256>>>(iV);
    cumsum_avg_kernel<<<dim3(NCHUNK_S, DD / 256, BB), 256>>>(iV);

    const dim3 ggrid(MTOT / BM, 1024 / BN);   // (256, 8)

    // 4: GEMM1  u = relu(avg @ W1 + b1)    g_act planes -> d_out planes
    gemm_split_kernel<<<ggrid, THREADS, SMEM_GEMM_TOTAL>>>(
        nullptr, act_hi, act_lo, p_w1h, p_w1l, b1,
        nullptr, nullptr, nullptr, nullptr, dout_hi, dout_lo, 1024, 0, 0);

    // 5: GEMM2  h = u @ W2 + b2            d_out planes -> g_act planes
    gemm_split_kernel<<<ggrid, THREADS, SMEM_GEMM_TOTAL>>>(
        nullptr, dout_hi, dout_lo, p_w2h, p_w2l, b2,
        nullptr, nullptr, nullptr, nullptr, act_hi, act_lo, 1024, 0, 1);

    // 6: GEMM3a (igate)  out = sigmoid([iQ,h] @ Wg[:, :D] + bg[:D]) * iQ
    gemm_split_kernel<<<ggrid, THREADS, SMEM_GEMM_TOTAL>>>(
        iQ, act_hi, act_lo, p_wgh, p_wgl, bg,
        iQ, nullptr, nullptr, out, nullptr, nullptr, 2048, 16, 2);

    // 7: GEMM3b (fgate)  out += sigmoid([iQ,h] @ Wg[:, D:] + bg[D:]) * h
    gemm_split_kernel<<<ggrid, THREADS, SMEM_GEMM_TOTAL>>>(
        iQ, act_hi, act_lo, p_wgh + (size_t)1024 * 2048, p_wgl + (size_t)1024 * 2048,
        bg + 1024, nullptr, act_hi, act_lo, out, nullptr, nullptr, 2048, 16, 3);
}